// round 16
// baseline (speedup 1.0000x reference)
#include <cuda_runtime.h>
#include <cuda_fp16.h>
#include <math.h>
#define NN 50000
#define MM 1250000
typedef unsigned long long ull;
__device__ float g_hA[NN*64];
__device__ float g_hB[NN*64];
__device__ float g_agg[NN*64];
__device__ __half2 g_hmA[NN*32];
__device__ __half2 g_hmB[NN*32];
__device__ __half2 g_Adh[NN*32];
__device__ __half2 g_Bdh[NN*32];
__device__ int2 g_sd[MM];
__device__ int2 g_csr[MM];
__device__ int g_cnt[NN];
__device__ int g_rowptr[NN+1];
__device__ int g_cursor[NN];
__device__ int g_is64;
__device__ int g_bsum[256];
__device__ int g_boff[256];
__device__ ull g_Wih_p[6144];
__device__ ull g_Whh_p[6144];
__device__ ull g_W2_p[1024];
__device__ ull g_W1e_p[160];
__device__ ull g_Whm_p[2048];
__device__ ull g_Wa_p[2048];
__device__ ull g_Wb_p[2048];
__device__ ull g_We_p[80];
__device__ float g_b1e[32];
__device__ float g_W2e[32];
__device__ float g_bhe[64];

__device__ __forceinline__ float sigf(float x){ return 1.f/(1.f+__expf(-x)); }
__device__ __forceinline__ ull ffma2(ull a, ull b, ull c){
  ull d; asm("fma.rn.f32x2 %0, %1, %2, %3;" : "=l"(d) : "l"(a), "l"(b), "l"(c)); return d;
}
__device__ __forceinline__ ull dup2(float v){
  ull r; asm("mov.b64 %0, {%1, %1};" : "=l"(r) : "f"(v)); return r;
}
__device__ __forceinline__ ull pk2(float lo, float hi){
  ull r; asm("mov.b64 %0, {%1, %2};" : "=l"(r) : "f"(lo), "f"(hi)); return r;
}
__device__ __forceinline__ void unpk2(ull p, float& lo, float& hi){
  asm("mov.b64 {%0, %1}, %2;" : "=f"(lo), "=f"(hi) : "l"(p));
}

__device__ __forceinline__ void gru_core(const ull* sWi, const ull* sWh, int lane,
    const float* ra0, const float* ra1, const float* rh0, const float* rh1,
    ull* R, ull* Z, ull* Ng, ull* Rh, ull* Zh, ull* Nh){
  #pragma unroll
  for (int i = 0; i < 4; i++){ R[i]=0ull; Z[i]=0ull; Ng[i]=0ull; Rh[i]=0ull; Zh[i]=0ull; Nh[i]=0ull; }
  #pragma unroll 4
  for (int k = 0; k < 32; k++){
    ull wir = sWi[(k*3+0)*32+lane], wiz = sWi[(k*3+1)*32+lane], win = sWi[(k*3+2)*32+lane];
    ull whr = sWh[(k*3+0)*32+lane], whz = sWh[(k*3+1)*32+lane], whn = sWh[(k*3+2)*32+lane];
    #pragma unroll
    for (int i = 0; i < 4; i++){
      ull av = dup2(__shfl_sync(~0u, ra0[i], k));
      ull hv = dup2(__shfl_sync(~0u, rh0[i], k));
      R[i] = ffma2(av, wir, R[i]); Z[i] = ffma2(av, wiz, Z[i]); Ng[i] = ffma2(av, win, Ng[i]);
      Rh[i] = ffma2(hv, whr, Rh[i]); Zh[i] = ffma2(hv, whz, Zh[i]); Nh[i] = ffma2(hv, whn, Nh[i]);
    }
  }
  #pragma unroll 4
  for (int k = 32; k < 64; k++){
    ull wir = sWi[(k*3+0)*32+lane], wiz = sWi[(k*3+1)*32+lane], win = sWi[(k*3+2)*32+lane];
    ull whr = sWh[(k*3+0)*32+lane], whz = sWh[(k*3+1)*32+lane], whn = sWh[(k*3+2)*32+lane];
    #pragma unroll
    for (int i = 0; i < 4; i++){
      ull av = dup2(__shfl_sync(~0u, ra1[i], k-32));
      ull hv = dup2(__shfl_sync(~0u, rh1[i], k-32));
      R[i] = ffma2(av, wir, R[i]); Z[i] = ffma2(av, wiz, Z[i]); Ng[i] = ffma2(av, win, Ng[i]);
      Rh[i] = ffma2(hv, whr, Rh[i]); Zh[i] = ffma2(hv, whz, Zh[i]); Nh[i] = ffma2(hv, whn, Nh[i]);
    }
  }
}

__global__ void k_init(const int* __restrict__ ei,
    const float* __restrict__ Wih, const float* __restrict__ Whh,
    const float* __restrict__ dW2, const float* __restrict__ dW1,
    const float* __restrict__ msW, const float* __restrict__ eW1,
    const float* __restrict__ eb1, const float* __restrict__ eW2,
    const float* __restrict__ Win, const float* __restrict__ bin,
    const float* __restrict__ u){
  int b = blockIdx.x, t = threadIdx.x;
  if (b < 196){
    int i = b*256 + t;
    if (i < NN) g_cnt[i] = 0;
  } else if (b == 196){
    __shared__ int nz;
    if (t == 0) nz = 0;
    __syncthreads();
    int c = 0;
    for (int i = t; i < 4096; i += 256) c += (ei[2*i+1] != 0);
    if (c) atomicAdd(&nz, 1);
    __syncthreads();
    if (t == 0) g_is64 = (nz == 0);
  } else if (b < 226){
    int i = (b-197)*256 + t;
    if (i < 6144){
      int jp = i & 31, r = i >> 5, g = r % 3, k = r / 3;
      g_Wih_p[i] = pk2(Wih[(g*64+jp)*64+k], Wih[(g*64+jp+32)*64+k]);
      g_Whh_p[i] = pk2(Whh[(g*64+jp)*64+k], Whh[(g*64+jp+32)*64+k]);
    } else if (i < 7168){
      int q = i - 6144, jp = q & 15, k = q >> 4;
      g_W2_p[q] = pk2(dW2[(2*jp)*64+k], dW2[(2*jp+1)*64+k]);
    } else if (i < 7328){
      int q = i - 7168, jp = q & 31, k = q >> 5;
      g_W1e_p[q] = pk2(dW1[(2*jp)*133+128+k], dW1[(2*jp+1)*133+128+k]);
    }
  } else if (b < 235){
    int i = (b-226)*256 + t;
    if (i < 2048){
      int l = i & 31, k = i >> 5;
      g_Whm_p[i] = pk2(msW[(2*l)*64+k], msW[(2*l+1)*64+k]);
    } else if (i < 2128){
      int q = i - 2048, ip = q & 15, k = q >> 4;
      g_We_p[q] = pk2(eW1[ip*16+k], eW1[(ip+16)*16+k]);
    } else if (i < 2160){
      int q = i - 2128;
      float acc = eb1[q];
      for (int k = 0; k < 11; k++) acc = fmaf(u[k], eW1[q*16+5+k], acc);
      g_b1e[q] = acc;
      g_W2e[q] = eW2[q];
    } else if (i < 2224){
      int j = i - 2160;
      float acc = bin[j];
      for (int k = 0; k < 11; k++) acc = fmaf(u[k], Win[j*23+12+k], acc);
      g_bhe[j] = acc;
    }
  } else {
    int i = (b-235)*256 + t;
    if (i < 2048){
      int l = i & 31, k = i >> 5;
      g_Wa_p[i] = pk2(dW1[(2*l)*133+k], dW1[(2*l+1)*133+k]);
    } else if (i < 4096){
      int q = i - 2048, l = q & 31, k = q >> 5;
      g_Wb_p[q] = pk2(dW1[(2*l)*133+64+k], dW1[(2*l+1)*133+64+k]);
    }
  }
}

__global__ void __launch_bounds__(256) k_count(const void* __restrict__ ei){
  int e = blockIdx.x*blockDim.x + threadIdx.x;
  if (e >= MM) return;
  int d;
  if (g_is64) d = (int)((const long long*)ei)[MM+e];
  else d = ((const int*)ei)[MM+e];
  atomicAdd(&g_cnt[d], 1);
}

__global__ void k_scan1(){
  int b = blockIdx.x, t = threadIdx.x;
  int i = b*256 + t;
  int v = (i < NN) ? g_cnt[i] : 0;
  __shared__ int ws[8];
  int lane = t & 31, wid = t >> 5;
  for (int o = 16; o >= 1; o >>= 1) v += __shfl_down_sync(~0u, v, o);
  if (lane == 0) ws[wid] = v;
  __syncthreads();
  if (t == 0){
    int s = 0;
    for (int w = 0; w < 8; w++) s += ws[w];
    g_bsum[b] = s;
  }
}
__global__ void k_scan2(){
  int t = threadIdx.x;
  int v = (t < 196) ? g_bsum[t] : 0;
  int lane = t & 31, wid = t >> 5;
  __shared__ int ws[8], wo[8];
  int x = v;
  for (int o = 1; o < 32; o <<= 1){ int uu = __shfl_up_sync(~0u, x, o); if (lane >= o) x += uu; }
  if (lane == 31) ws[wid] = x;
  __syncthreads();
  if (t == 0){
    int s = 0;
    for (int w = 0; w < 8; w++){ wo[w] = s; s += ws[w]; }
  }
  __syncthreads();
  g_boff[t] = x - v + wo[wid];
}
__global__ void k_scan3(){
  int b = blockIdx.x, t = threadIdx.x;
  int i = b*256 + t;
  int v = (i < NN) ? g_cnt[i] : 0;
  int lane = t & 31, wid = t >> 5;
  __shared__ int ws[8], wo[8];
  int x = v;
  for (int o = 1; o < 32; o <<= 1){ int uu = __shfl_up_sync(~0u, x, o); if (lane >= o) x += uu; }
  if (lane == 31) ws[wid] = x;
  __syncthreads();
  if (t == 0){
    int s = 0;
    for (int w = 0; w < 8; w++){ wo[w] = s; s += ws[w]; }
  }
  __syncthreads();
  int excl = x - v + wo[wid] + g_boff[b];
  if (i < NN){ g_cursor[i] = excl; g_rowptr[i+1] = excl + v; }
  if (i == 0) g_rowptr[0] = 0;
}

__global__ void __launch_bounds__(256) k_prep2(const void* __restrict__ ei,
    const float* __restrict__ ea, const float* __restrict__ b2){
  __shared__ float sEA[1280];
  __shared__ ull sWe[80], sB1[16];
  __shared__ float sW2[32];
  __shared__ float sb2;
  int t = threadIdx.x;
  int base = blockIdx.x*256;
  for (int i = t; i < 80; i += 256) sWe[i] = g_We_p[i];
  if (t < 16) sB1[t] = pk2(g_b1e[t], g_b1e[t+16]);
  if (t < 32) sW2[t] = g_W2e[t];
  if (t == 0) sb2 = b2[0];
  int lim = MM*5 - base*5;
  for (int i = t; i < 1280 && i < lim; i += 256) sEA[i] = ea[base*5+i];
  __syncthreads();
  int e = base + t;
  if (e >= MM) return;
  int s, d;
  if (g_is64){
    const long long* p = (const long long*)ei;
    s = (int)p[e]; d = (int)p[MM+e];
  } else {
    const int* p = (const int*)ei;
    s = p[e]; d = p[MM+e];
  }
  g_sd[e] = make_int2(s, d);
  float f[5];
  for (int k = 0; k < 5; k++) f[k] = sEA[t*5+k];
  ull ap[16];
  for (int i = 0; i < 16; i++) ap[i] = sB1[i];
  for (int k = 0; k < 5; k++){
    ull fv = dup2(f[k]);
    for (int i = 0; i < 16; i++) ap[i] = ffma2(fv, sWe[k*16+i], ap[i]);
  }
  float acc = sb2;
  for (int i = 0; i < 16; i++){
    float lo, hi;
    unpk2(ap[i], lo, hi);
    acc = fmaf(fmaxf(lo, 0.f), sW2[i], acc);
    acc = fmaf(fmaxf(hi, 0.f), sW2[i+16], acc);
  }
  int p = atomicAdd(&g_cursor[d], 1);
  g_csr[p] = make_int2(s, __float_as_int(sigf(acc)));
}

__global__ void k_h2(const float* __restrict__ x, const float* __restrict__ Win){
  __shared__ float sW[768], sb[64];
  int t = threadIdx.x;
  for (int i = t; i < 768; i += blockDim.x){ int j = i/12, k = i%12; sW[i] = Win[j*23+k]; }
  if (t < 64) sb[t] = g_bhe[t];
  __syncthreads();
  int idx = blockIdx.x*blockDim.x + t;
  if (idx >= NN*64) return;
  int node = idx >> 6, j = idx & 63;
  const float* w = &sW[j*12];
  const float* xr = &x[node*12];
  float acc = sb[j];
  for (int k = 0; k < 12; k++) acc = fmaf(xr[k], w[k], acc);
  g_hA[idx] = tanhf(acc);
}

__global__ void k_hm0(const float* __restrict__ hin, __half2* __restrict__ hmout,
    const float* __restrict__ b){
  __shared__ ull sW[2048];
  __shared__ ull sbp[32];
  int t = threadIdx.x;
  for (int i = t; i < 2048; i += blockDim.x) sW[i] = g_Whm_p[i];
  if (t < 32) sbp[t] = pk2(b[2*t], b[2*t+1]);
  __syncthreads();
  int lane = t & 31;
  int wg = (blockIdx.x*blockDim.x + t) >> 5;
  int nw = (gridDim.x*blockDim.x) >> 5;
  for (int n = wg; n < NN; n += nw){
    float v0 = hin[(n<<6)+lane], v1 = hin[(n<<6)+32+lane];
    ull ap = sbp[lane];
    #pragma unroll 8
    for (int k = 0; k < 32; k++) ap = ffma2(dup2(__shfl_sync(~0u, v0, k)), sW[k*32+lane], ap);
    #pragma unroll 8
    for (int k = 0; k < 32; k++) ap = ffma2(dup2(__shfl_sync(~0u, v1, k)), sW[(32+k)*32+lane], ap);
    float lo, hi;
    unpk2(ap, lo, hi);
    hmout[n*32+lane] = __floats2half2_rn(fmaxf(lo, 0.f), fmaxf(hi, 0.f));
  }
}

__global__ void k_agg(const __half2* __restrict__ hmin){
  int w = (blockIdx.x*blockDim.x + threadIdx.x) >> 5;
  int lane = threadIdx.x & 31;
  if (w >= NN) return;
  int beg = g_rowptr[w], end = g_rowptr[w+1];
  float ax = 0.f, ay = 0.f;
  int i = beg;
  for (; i + 7 < end; i += 8){
    int2 ee[8];
    float2 ff[8];
    #pragma unroll
    for (int j = 0; j < 8; j++) ee[j] = g_csr[i+j];
    #pragma unroll
    for (int j = 0; j < 8; j++) ff[j] = __half22float2(hmin[(size_t)ee[j].x*32+lane]);
    #pragma unroll
    for (int j = 0; j < 8; j++){
      float a = __int_as_float(ee[j].y);
      ax = fmaf(a, ff[j].x, ax);
      ay = fmaf(a, ff[j].y, ay);
    }
  }
  for (; i < end; i++){
    int2 e0 = g_csr[i];
    float a0 = __int_as_float(e0.y);
    float2 f0 = __half22float2(hmin[(size_t)e0.x*32+lane]);
    ax = fmaf(a0, f0.x, ax);
    ay = fmaf(a0, f0.y, ay);
  }
  float inv = 1.f / fmaxf((float)(end - beg), 1.f);
  ((float2*)g_agg)[w*32+lane] = make_float2(ax*inv, ay*inv);
}

#define GRUF_SMEM (14336*8)
__global__ void __launch_bounds__(256,2) k_gruf(const float* __restrict__ hin,
    float* __restrict__ hout, __half2* __restrict__ hmout,
    const float* __restrict__ bih, const float* __restrict__ bhh,
    const float* __restrict__ msb){
  extern __shared__ ull sw[];
  ull* sWi = sw;
  ull* sWh = sw + 6144;
  ull* sHm = sw + 12288;
  __shared__ float sbi[192], sbh[192];
  __shared__ ull sMb[32];
  int t = threadIdx.x;
  for (int i = t; i < 6144; i += 256){ sWi[i] = g_Wih_p[i]; sWh[i] = g_Whh_p[i]; }
  for (int i = t; i < 2048; i += 256) sHm[i] = g_Whm_p[i];
  for (int i = t; i < 192; i += 256){ sbi[i] = bih[i]; sbh[i] = bhh[i]; }
  if (t < 32) sMb[t] = pk2(msb[2*t], msb[2*t+1]);
  __syncthreads();
  int w = t >> 5, lane = t & 31;
  int nchunk = (NN + 31) / 32;
  for (int c = blockIdx.x; c < nchunk; c += gridDim.x){
    int nbase = c*32 + w*4;
    float ra0[4], ra1[4], rh0[4], rh1[4];
    #pragma unroll
    for (int i = 0; i < 4; i++){
      int n = min(nbase + i, NN - 1);
      ra0[i] = g_agg[(n<<6)+lane];
      ra1[i] = g_agg[(n<<6)+32+lane];
      rh0[i] = hin[(n<<6)+lane];
      rh1[i] = hin[(n<<6)+32+lane];
    }
    ull R[4], Z[4], Ng[4], Rh[4], Zh[4], Nh[4];
    gru_core(sWi, sWh, lane, ra0, ra1, rh0, rh1, R, Z, Ng, Rh, Zh, Nh);
    #pragma unroll
    for (int i = 0; i < 4; i++){
      int n = nbase + i;
      bool ok = (n < NN);
      float aL, aH, bL, bH;
      unpk2(R[i], aL, aH);
      unpk2(Rh[i], bL, bH);
      float rL = sigf(aL + sbi[lane] + bL + sbh[lane]);
      float rH = sigf(aH + sbi[lane+32] + bH + sbh[lane+32]);
      unpk2(Z[i], aL, aH);
      unpk2(Zh[i], bL, bH);
      float zL = sigf(aL + sbi[64+lane] + bL + sbh[64+lane]);
      float zH = sigf(aH + sbi[96+lane] + bH + sbh[96+lane]);
      unpk2(Ng[i], aL, aH);
      unpk2(Nh[i], bL, bH);
      float ngL = tanhf(aL + sbi[128+lane] + rL*(bL + sbh[128+lane]));
      float ngH = tanhf(aH + sbi[160+lane] + rH*(bH + sbh[160+lane]));
      float hnL = (1.f - zL)*ngL + zL*rh0[i];
      float hnH = (1.f - zH)*ngH + zH*rh1[i];
      if (ok){
        hout[(n<<6)+lane] = hnL;
        hout[(n<<6)+32+lane] = hnH;
      }
      ull ap = sMb[lane];
      #pragma unroll 8
      for (int k = 0; k < 32; k++) ap = ffma2(dup2(__shfl_sync(~0u, hnL, k)), sHm[k*32+lane], ap);
      #pragma unroll 8
      for (int k = 0; k < 32; k++) ap = ffma2(dup2(__shfl_sync(~0u, hnH, k)), sHm[(32+k)*32+lane], ap);
      float lo, hi;
      unpk2(ap, lo, hi);
      if (ok) hmout[n*32+lane] = __floats2half2_rn(fmaxf(lo, 0.f), fmaxf(hi, 0.f));
    }
  }
}

#define GRU_SMEM (12288*8)
__global__ void __launch_bounds__(256,2) k_gru(const float* __restrict__ hin,
    float* __restrict__ hout, const float* __restrict__ bih,
    const float* __restrict__ bhh){
  extern __shared__ ull sw[];
  ull* sWi = sw;
  ull* sWh = sw + 6144;
  __shared__ float sbi[192], sbh[192];
  int t = threadIdx.x;
  for (int i = t; i < 6144; i += 256){ sWi[i] = g_Wih_p[i]; sWh[i] = g_Whh_p[i]; }
  for (int i = t; i < 192; i += 256){ sbi[i] = bih[i]; sbh[i] = bhh[i]; }
  __syncthreads();
  int w = t >> 5, lane = t & 31;
  int nchunk = (NN + 31) / 32;
  for (int c = blockIdx.x; c < nchunk; c += gridDim.x){
    int nbase = c*32 + w*4;
    float ra0[4], ra1[4], rh0[4], rh1[4];
    #pragma unroll
    for (int i = 0; i < 4; i++){
      int n = min(nbase + i, NN - 1);
      ra0[i] = g_agg[(n<<6)+lane];
      ra1[i] = g_agg[(n<<6)+32+lane];
      rh0[i] = hin[(n<<6)+lane];
      rh1[i] = hin[(n<<6)+32+lane];
    }
    ull R[4], Z[4], Ng[4], Rh[4], Zh[4], Nh[4];
    gru_core(sWi, sWh, lane, ra0, ra1, rh0, rh1, R, Z, Ng, Rh, Zh, Nh);
    #pragma unroll
    for (int i = 0; i < 4; i++){
      int n = nbase + i;
      if (n >= NN) break;
      float aL, aH, bL, bH;
      unpk2(R[i], aL, aH);
      unpk2(Rh[i], bL, bH);
      float rL = sigf(aL + sbi[lane] + bL + sbh[lane]);
      float rH = sigf(aH + sbi[lane+32] + bH + sbh[lane+32]);
      unpk2(Z[i], aL, aH);
      unpk2(Zh[i], bL, bH);
      float zL = sigf(aL + sbi[64+lane] + bL + sbh[64+lane]);
      float zH = sigf(aH + sbi[96+lane] + bH + sbh[96+lane]);
      unpk2(Ng[i], aL, aH);
      unpk2(Nh[i], bL, bH);
      float ngL = tanhf(aL + sbi[128+lane] + rL*(bL + sbh[128+lane]));
      float ngH = tanhf(aH + sbi[160+lane] + rH*(bH + sbh[160+lane]));
      hout[(n<<6)+lane] = (1.f - zL)*ngL + zL*rh0[i];
      hout[(n<<6)+32+lane] = (1.f - zH)*ngH + zH*rh1[i];
    }
  }
}

__global__ void k_AB(const float* __restrict__ hin, const float* __restrict__ b1){
  __shared__ ull sWa[2048], sWb[2048];
  __shared__ ull sbp[32];
  int t = threadIdx.x;
  for (int i = t; i < 2048; i += blockDim.x){ sWa[i] = g_Wa_p[i]; sWb[i] = g_Wb_p[i]; }
  if (t < 32) sbp[t] = pk2(b1[2*t], b1[2*t+1]);
  __syncthreads();
  int lane = t & 31;
  int wg = (blockIdx.x*blockDim.x + t) >> 5;
  int nw = (gridDim.x*blockDim.x) >> 5;
  for (int n = wg; n < NN; n += nw){
    float v0 = hin[(n<<6)+lane], v1 = hin[(n<<6)+32+lane];
    ull aA = sbp[lane], aB = 0ull;
    #pragma unroll 8
    for (int k = 0; k < 32; k++){
      ull v = dup2(__shfl_sync(~0u, v0, k));
      aA = ffma2(v, sWa[k*32+lane], aA);
      aB = ffma2(v, sWb[k*32+lane], aB);
    }
    #pragma unroll 8
    for (int k = 0; k < 32; k++){
      ull v = dup2(__shfl_sync(~0u, v1, k));
      aA = ffma2(v, sWa[(32+k)*32+lane], aA);
      aB = ffma2(v, sWb[(32+k)*32+lane], aB);
    }
    float alo, ahi, blo, bhi;
    unpk2(aA, alo, ahi);
    unpk2(aB, blo, bhi);
    g_Adh[n*32+lane] = __floats2half2_rn(alo, ahi);
    g_Bdh[n*32+lane] = __floats2half2_rn(blo, bhi);
  }
}

__global__ void __launch_bounds__(256) k_dec(const float* __restrict__ ea,
    float* __restrict__ out, const float* __restrict__ b2,
    const float* __restrict__ W3, const float* __restrict__ b3){
  __shared__ __align__(16) ull sW1[160];
  __shared__ __align__(16) ull sW2[1024];
  __shared__ float sW3[128];
  __shared__ float sb2[32], sb3[4];
  __shared__ float sEA[1280];
  int t = threadIdx.x;
  int base = blockIdx.x*256;
  for (int i = t; i < 160; i += 256) sW1[i] = g_W1e_p[i];
  for (int i = t; i < 1024; i += 256) sW2[i] = g_W2_p[i];
  for (int i = t; i < 128; i += 256) sW3[i] = W3[i];
  if (t < 32) sb2[t] = b2[t];
  if (t < 4) sb3[t] = b3[t];
  int lim = MM*5 - base*5;
  for (int i = t; i < 1280 && i < lim; i += 256) sEA[i] = ea[base*5+i];
  __syncthreads();
  int e = base + t;
  if (e >= MM) return;
  int2 sd = g_sd[e];
  const uint4* pA = (const uint4*)&g_Adh[(size_t)sd.x*32];
  const uint4* pB = (const uint4*)&g_Bdh[(size_t)sd.y*32];
  ull s1p[32];
  #pragma unroll
  for (int q = 0; q < 8; q++){
    uint4 av = __ldg(&pA[q]);
    uint4 bv = __ldg(&pB[q]);
    float2 fa, fb;
    fa = __half22float2(*(__half2*)&av.x);
    fb = __half22float2(*(__half2*)&bv.x);
    s1p[4*q+0] = pk2(fa.x+fb.x, fa.y+fb.y);
    fa = __half22float2(*(__half2*)&av.y);
    fb = __half22float2(*(__half2*)&bv.y);
    s1p[4*q+1] = pk2(fa.x+fb.x, fa.y+fb.y);
    fa = __half22float2(*(__half2*)&av.z);
    fb = __half22float2(*(__half2*)&bv.z);
    s1p[4*q+2] = pk2(fa.x+fb.x, fa.y+fb.y);
    fa = __half22float2(*(__half2*)&av.w);
    fb = __half22float2(*(__half2*)&bv.w);
    s1p[4*q+3] = pk2(fa.x+fb.x, fa.y+fb.y);
  }
  const ulonglong2* w1 = (const ulonglong2*)sW1;
  #pragma unroll
  for (int k = 0; k < 5; k++){
    ull ev = dup2(sEA[t*5+k]);
    #pragma unroll
    for (int q = 0; q < 16; q++){
      ulonglong2 wq = w1[k*16+q];
      s1p[2*q] = ffma2(ev, wq.x, s1p[2*q]);
      s1p[2*q+1] = ffma2(ev, wq.y, s1p[2*q+1]);
    }
  }
  float s1[64];
  #pragma unroll
  for (int p = 0; p < 32; p++){
    float lo, hi;
    unpk2(s1p[p], lo, hi);
    s1[2*p] = fmaxf(lo, 0.f);
    s1[2*p+1] = fmaxf(hi, 0.f);
  }
  ull a2p[16];
  #pragma unroll
  for (int jp = 0; jp < 16; jp++) a2p[jp] = pk2(sb2[2*jp], sb2[2*jp+1]);
  const ulonglong2* w2 = (const ulonglong2*)sW2;
  #pragma unroll 8
  for (int k = 0; k < 64; k++){
    ull sdv = dup2(s1[k]);
    #pragma unroll
    for (int q = 0; q < 8; q++){
      ulonglong2 wq = w2[k*8+q];
      a2p[2*q] = ffma2(sdv, wq.x, a2p[2*q]);
      a2p[2*q+1] = ffma2(sdv, wq.y, a2p[2*q+1]);
    }
  }
  float a2[32];
  #pragma unroll
  for (int jp = 0; jp < 16; jp++){
    float lo, hi;
    unpk2(a2p[jp], lo, hi);
    a2[2*jp] = fmaxf(lo, 0.f);
    a2[2*jp+1] = fmaxf(hi, 0.f);
  }
  float o0 = sb3[0], o1 = sb3[1], o2 = sb3[2], o3 = sb3[3];
  #pragma unroll
  for (int q = 0; q < 32; q++){
    float v = a2[q];
    o0 = fmaf(v, sW3[q], o0);
    o1 = fmaf(v, sW3[32+q], o1);
    o2 = fmaf(v, sW3[64+q], o2);
    o3 = fmaf(v, sW3[96+q], o3);
  }
  ((float4*)out)[e] = make_float4(o0, o1, o2, o3);
}

extern "C" void kernel_launch(void* const* d_in, const int* in_sizes, int n_in,
                              void* d_out, int out_size){
  (void)in_sizes; (void)n_in; (void)out_size;
  const float* x   = (const float*)d_in[0];
  const void*  ei  = d_in[1];
  const float* ea  = (const float*)d_in[2];
  const float* u   = (const float*)d_in[3];
  const float* Win = (const float*)d_in[4];
  const float* bin = (const float*)d_in[5];
  const float* eW1 = (const float*)d_in[6];
  const float* eb1 = (const float*)d_in[7];
  const float* eW2 = (const float*)d_in[8];
  const float* eb2 = (const float*)d_in[9];
  const float* msW = (const float*)d_in[10];
  const float* msb = (const float*)d_in[11];
  const float* Wih = (const float*)d_in[12];
  const float* bih = (const float*)d_in[13];
  const float* Whh = (const float*)d_in[14];
  const float* bhh = (const float*)d_in[15];
  const float* dW1 = (const float*)d_in[16];
  const float* db1 = (const float*)d_in[17];
  const float* dW2 = (const float*)d_in[18];
  const float* db2 = (const float*)d_in[19];
  const float* dW3 = (const float*)d_in[20];
  const float* db3 = (const float*)d_in[21];
  float* out = (float*)d_out;

  static int init_done = 0;
  static cudaStream_t s1;
  static cudaEvent_t evA, evB;
  if (!init_done){
    cudaFuncSetAttribute(k_gru,  cudaFuncAttributeMaxDynamicSharedMemorySize, GRU_SMEM);
    cudaFuncSetAttribute(k_gruf, cudaFuncAttributeMaxDynamicSharedMemorySize, GRUF_SMEM);
    cudaStreamCreateWithFlags(&s1, cudaStreamNonBlocking);
    cudaEventCreateWithFlags(&evA, cudaEventDisableTiming);
    cudaEventCreateWithFlags(&evB, cudaEventDisableTiming);
    init_done = 1;
  }

  float *hA_p = 0, *hB_p = 0;
  __half2 *hmA_p = 0, *hmB_p = 0;
  cudaGetSymbolAddress((void**)&hA_p, g_hA);
  cudaGetSymbolAddress((void**)&hB_p, g_hB);
  cudaGetSymbolAddress((void**)&hmA_p, g_hmA);
  cudaGetSymbolAddress((void**)&hmB_p, g_hmB);

  k_init<<<251, 256>>>((const int*)ei, Wih, Whh, dW2, dW1, msW, eW1, eb1, eW2, Win, bin, u);

  cudaEventRecord(evA, 0);
  cudaStreamWaitEvent(s1, evA, 0);

  k_h2<<<(NN*64 + 255)/256, 256, 0, s1>>>(x, Win);
  k_hm0<<<1184, 256, 0, s1>>>(hA_p, hmA_p, msb);
  cudaEventRecord(evB, s1);

  k_count<<<(MM + 255)/256, 256>>>(ei);
  k_scan1<<<196, 256>>>();
  k_scan2<<<1, 256>>>();
  k_scan3<<<196, 256>>>();
  k_prep2<<<(MM + 255)/256, 256>>>(ei, ea, eb2);

  cudaStreamWaitEvent(0, evB, 0);

  const int GRID_AGG = (NN*32 + 255)/256;
  k_agg<<<GRID_AGG, 256>>>(hmA_p);
  k_gruf<<<296, 256, GRUF_SMEM>>>(hA_p, hB_p, hmB_p, bih, bhh, msb);

  k_agg<<<GRID_AGG, 256>>>(hmB_p);
  k_gruf<<<296, 256, GRUF_SMEM>>>(hB_p, hA_p, hmA_p, bih, bhh, msb);

  k_agg<<<GRID_AGG, 256>>>(hmA_p);
  k_gru<<<296, 256, GRU_SMEM>>>(hA_p, hB_p, bih, bhh);

  k_AB<<<1184, 256>>>(hB_p, db1);
  k_dec<<<(MM + 255)/256, 256>>>(ea, out, db2, dW3, db3);
}

// round 17
// speedup vs baseline: 1.0022x; 1.0022x over previous
#include <cuda_runtime.h>
#include <cuda_fp16.h>
#include <math.h>
#define NN 50000
#define MM 1250000
typedef unsigned long long ull;
__device__ float g_hA[NN*64];
__device__ float g_hB[NN*64];
__device__ float g_agg[NN*64];
__device__ __half2 g_hmA[NN*32];
__device__ __half2 g_hmB[NN*32];
__device__ __half2 g_Adh[NN*32];
__device__ __half2 g_Bdh[NN*32];
__device__ int2 g_sd[MM];
__device__ int2 g_csr[MM];
__device__ int g_cnt[NN];
__device__ int g_rowptr[NN+1];
__device__ int g_cursor[NN];
__device__ int g_is64;
__device__ int g_bsum[256];
__device__ int g_boff[256];
__device__ ull g_Wih_p[6144];
__device__ ull g_Whh_p[6144];
__device__ ull g_W2_p[1024];
__device__ ull g_W1e_p[160];
__device__ ull g_Whm_p[2048];
__device__ ull g_Wa_p[2048];
__device__ ull g_Wb_p[2048];
__device__ ull g_We_p[80];
__device__ float g_b1e[32];
__device__ float g_W2e[32];
__device__ float g_bhe[64];

__device__ __forceinline__ float sigf(float x){ return 1.f/(1.f+__expf(-x)); }
__device__ __forceinline__ ull ffma2(ull a, ull b, ull c){
  ull d; asm("fma.rn.f32x2 %0, %1, %2, %3;" : "=l"(d) : "l"(a), "l"(b), "l"(c)); return d;
}
__device__ __forceinline__ ull dup2(float v){
  ull r; asm("mov.b64 %0, {%1, %1};" : "=l"(r) : "f"(v)); return r;
}
__device__ __forceinline__ ull pk2(float lo, float hi){
  ull r; asm("mov.b64 %0, {%1, %2};" : "=l"(r) : "f"(lo), "f"(hi)); return r;
}
__device__ __forceinline__ void unpk2(ull p, float& lo, float& hi){
  asm("mov.b64 {%0, %1}, %2;" : "=f"(lo), "=f"(hi) : "l"(p));
}

__device__ __forceinline__ void gru_core(const ull* sWi, const ull* sWh, int lane,
    const float* ra0, const float* ra1, const float* rh0, const float* rh1,
    ull* R, ull* Z, ull* Ng, ull* Rh, ull* Zh, ull* Nh){
  #pragma unroll
  for (int i = 0; i < 4; i++){ R[i]=0ull; Z[i]=0ull; Ng[i]=0ull; Rh[i]=0ull; Zh[i]=0ull; Nh[i]=0ull; }
  #pragma unroll 4
  for (int k = 0; k < 32; k++){
    ull wir = sWi[(k*3+0)*32+lane], wiz = sWi[(k*3+1)*32+lane], win = sWi[(k*3+2)*32+lane];
    ull whr = sWh[(k*3+0)*32+lane], whz = sWh[(k*3+1)*32+lane], whn = sWh[(k*3+2)*32+lane];
    #pragma unroll
    for (int i = 0; i < 4; i++){
      ull av = dup2(__shfl_sync(~0u, ra0[i], k));
      ull hv = dup2(__shfl_sync(~0u, rh0[i], k));
      R[i] = ffma2(av, wir, R[i]); Z[i] = ffma2(av, wiz, Z[i]); Ng[i] = ffma2(av, win, Ng[i]);
      Rh[i] = ffma2(hv, whr, Rh[i]); Zh[i] = ffma2(hv, whz, Zh[i]); Nh[i] = ffma2(hv, whn, Nh[i]);
    }
  }
  #pragma unroll 4
  for (int k = 32; k < 64; k++){
    ull wir = sWi[(k*3+0)*32+lane], wiz = sWi[(k*3+1)*32+lane], win = sWi[(k*3+2)*32+lane];
    ull whr = sWh[(k*3+0)*32+lane], whz = sWh[(k*3+1)*32+lane], whn = sWh[(k*3+2)*32+lane];
    #pragma unroll
    for (int i = 0; i < 4; i++){
      ull av = dup2(__shfl_sync(~0u, ra1[i], k-32));
      ull hv = dup2(__shfl_sync(~0u, rh1[i], k-32));
      R[i] = ffma2(av, wir, R[i]); Z[i] = ffma2(av, wiz, Z[i]); Ng[i] = ffma2(av, win, Ng[i]);
      Rh[i] = ffma2(hv, whr, Rh[i]); Zh[i] = ffma2(hv, whz, Zh[i]); Nh[i] = ffma2(hv, whn, Nh[i]);
    }
  }
}

__global__ void k_init(const int* __restrict__ ei,
    const float* __restrict__ Wih, const float* __restrict__ Whh,
    const float* __restrict__ dW2, const float* __restrict__ dW1,
    const float* __restrict__ msW, const float* __restrict__ eW1,
    const float* __restrict__ eb1, const float* __restrict__ eW2,
    const float* __restrict__ Win, const float* __restrict__ bin,
    const float* __restrict__ u){
  int b = blockIdx.x, t = threadIdx.x;
  if (b < 196){
    int i = b*256 + t;
    if (i < NN) g_cnt[i] = 0;
  } else if (b == 196){
    __shared__ int nz;
    if (t == 0) nz = 0;
    __syncthreads();
    int c = 0;
    for (int i = t; i < 4096; i += 256) c += (ei[2*i+1] != 0);
    if (c) atomicAdd(&nz, 1);
    __syncthreads();
    if (t == 0) g_is64 = (nz == 0);
  } else if (b < 226){
    int i = (b-197)*256 + t;
    if (i < 6144){
      int jp = i & 31, r = i >> 5, g = r % 3, k = r / 3;
      g_Wih_p[i] = pk2(Wih[(g*64+jp)*64+k], Wih[(g*64+jp+32)*64+k]);
      g_Whh_p[i] = pk2(Whh[(g*64+jp)*64+k], Whh[(g*64+jp+32)*64+k]);
    } else if (i < 7168){
      int q = i - 6144, jp = q & 15, k = q >> 4;
      g_W2_p[q] = pk2(dW2[(2*jp)*64+k], dW2[(2*jp+1)*64+k]);
    } else if (i < 7328){
      int q = i - 7168, jp = q & 31, k = q >> 5;
      g_W1e_p[q] = pk2(dW1[(2*jp)*133+128+k], dW1[(2*jp+1)*133+128+k]);
    }
  } else if (b < 235){
    int i = (b-226)*256 + t;
    if (i < 2048){
      int l = i & 31, k = i >> 5;
      g_Whm_p[i] = pk2(msW[(2*l)*64+k], msW[(2*l+1)*64+k]);
    } else if (i < 2128){
      int q = i - 2048, ip = q & 15, k = q >> 4;
      g_We_p[q] = pk2(eW1[ip*16+k], eW1[(ip+16)*16+k]);
    } else if (i < 2160){
      int q = i - 2128;
      float acc = eb1[q];
      for (int k = 0; k < 11; k++) acc = fmaf(u[k], eW1[q*16+5+k], acc);
      g_b1e[q] = acc;
      g_W2e[q] = eW2[q];
    } else if (i < 2224){
      int j = i - 2160;
      float acc = bin[j];
      for (int k = 0; k < 11; k++) acc = fmaf(u[k], Win[j*23+12+k], acc);
      g_bhe[j] = acc;
    }
  } else {
    int i = (b-235)*256 + t;
    if (i < 2048){
      int l = i & 31, k = i >> 5;
      g_Wa_p[i] = pk2(dW1[(2*l)*133+k], dW1[(2*l+1)*133+k]);
    } else if (i < 4096){
      int q = i - 2048, l = q & 31, k = q >> 5;
      g_Wb_p[q] = pk2(dW1[(2*l)*133+64+k], dW1[(2*l+1)*133+64+k]);
    }
  }
}

__global__ void __launch_bounds__(256) k_count(const void* __restrict__ ei){
  int p = blockIdx.x*blockDim.x + threadIdx.x;
  int e = p*2;
  if (e >= MM) return;
  int d0, d1;
  bool two = (e + 1 < MM);
  if (g_is64){
    const longlong2* pp = (const longlong2*)((const long long*)ei + MM);
    longlong2 v = pp[p];
    d0 = (int)v.x; d1 = (int)v.y;
  } else {
    const int2* pp = (const int2*)((const int*)ei + MM);
    int2 v = pp[p];
    d0 = v.x; d1 = v.y;
  }
  atomicAdd(&g_cnt[d0], 1);
  if (two) atomicAdd(&g_cnt[d1], 1);
}

__global__ void k_scan1(){
  int b = blockIdx.x, t = threadIdx.x;
  int i = b*256 + t;
  int v = (i < NN) ? g_cnt[i] : 0;
  __shared__ int ws[8];
  int lane = t & 31, wid = t >> 5;
  v = __reduce_add_sync(~0u, v);
  if (lane == 0) ws[wid] = v;
  __syncthreads();
  if (t == 0){
    int s = 0;
    for (int w = 0; w < 8; w++) s += ws[w];
    g_bsum[b] = s;
  }
}
__global__ void k_scan2(){
  int t = threadIdx.x;
  int v = (t < 196) ? g_bsum[t] : 0;
  int lane = t & 31, wid = t >> 5;
  __shared__ int ws[8], wo[8];
  int x = v;
  for (int o = 1; o < 32; o <<= 1){ int uu = __shfl_up_sync(~0u, x, o); if (lane >= o) x += uu; }
  if (lane == 31) ws[wid] = x;
  __syncthreads();
  if (t == 0){
    int s = 0;
    for (int w = 0; w < 8; w++){ wo[w] = s; s += ws[w]; }
  }
  __syncthreads();
  g_boff[t] = x - v + wo[wid];
}
__global__ void k_scan3(){
  int b = blockIdx.x, t = threadIdx.x;
  int i = b*256 + t;
  int v = (i < NN) ? g_cnt[i] : 0;
  int lane = t & 31, wid = t >> 5;
  __shared__ int ws[8], wo[8];
  int x = v;
  for (int o = 1; o < 32; o <<= 1){ int uu = __shfl_up_sync(~0u, x, o); if (lane >= o) x += uu; }
  if (lane == 31) ws[wid] = x;
  __syncthreads();
  if (t == 0){
    int s = 0;
    for (int w = 0; w < 8; w++){ wo[w] = s; s += ws[w]; }
  }
  __syncthreads();
  int excl = x - v + wo[wid] + g_boff[b];
  if (i < NN){ g_cursor[i] = excl; g_rowptr[i+1] = excl + v; }
  if (i == 0) g_rowptr[0] = 0;
}

__global__ void __launch_bounds__(256) k_prep2(const void* __restrict__ ei,
    const float* __restrict__ ea, const float* __restrict__ b2){
  __shared__ float sEA[1280];
  __shared__ ull sWe[80], sB1[16];
  __shared__ float sW2[32];
  __shared__ float sb2;
  int t = threadIdx.x;
  int base = blockIdx.x*256;
  for (int i = t; i < 80; i += 256) sWe[i] = g_We_p[i];
  if (t < 16) sB1[t] = pk2(g_b1e[t], g_b1e[t+16]);
  if (t < 32) sW2[t] = g_W2e[t];
  if (t == 0) sb2 = b2[0];
  int lim = MM*5 - base*5;
  for (int i = t; i < 1280 && i < lim; i += 256) sEA[i] = ea[base*5+i];
  __syncthreads();
  int e = base + t;
  if (e >= MM) return;
  int s, d;
  if (g_is64){
    const long long* p = (const long long*)ei;
    s = (int)p[e]; d = (int)p[MM+e];
  } else {
    const int* p = (const int*)ei;
    s = p[e]; d = p[MM+e];
  }
  g_sd[e] = make_int2(s, d);
  float f[5];
  for (int k = 0; k < 5; k++) f[k] = sEA[t*5+k];
  ull ap[16];
  for (int i = 0; i < 16; i++) ap[i] = sB1[i];
  for (int k = 0; k < 5; k++){
    ull fv = dup2(f[k]);
    for (int i = 0; i < 16; i++) ap[i] = ffma2(fv, sWe[k*16+i], ap[i]);
  }
  float acc = sb2;
  for (int i = 0; i < 16; i++){
    float lo, hi;
    unpk2(ap[i], lo, hi);
    acc = fmaf(fmaxf(lo, 0.f), sW2[i], acc);
    acc = fmaf(fmaxf(hi, 0.f), sW2[i+16], acc);
  }
  int p = atomicAdd(&g_cursor[d], 1);
  g_csr[p] = make_int2(s, __float_as_int(sigf(acc)));
}

__global__ void k_h2(const float* __restrict__ x, const float* __restrict__ Win){
  __shared__ float sW[768], sb[64];
  int t = threadIdx.x;
  for (int i = t; i < 768; i += blockDim.x){ int j = i/12, k = i%12; sW[i] = Win[j*23+k]; }
  if (t < 64) sb[t] = g_bhe[t];
  __syncthreads();
  int idx = blockIdx.x*blockDim.x + t;
  if (idx >= NN*64) return;
  int node = idx >> 6, j = idx & 63;
  const float* w = &sW[j*12];
  const float* xr = &x[node*12];
  float acc = sb[j];
  for (int k = 0; k < 12; k++) acc = fmaf(xr[k], w[k], acc);
  g_hA[idx] = tanhf(acc);
}

__global__ void k_hm0(const float* __restrict__ hin, __half2* __restrict__ hmout,
    const float* __restrict__ b){
  __shared__ ull sW[2048];
  __shared__ ull sbp[32];
  int t = threadIdx.x;
  for (int i = t; i < 2048; i += blockDim.x) sW[i] = g_Whm_p[i];
  if (t < 32) sbp[t] = pk2(b[2*t], b[2*t+1]);
  __syncthreads();
  int lane = t & 31;
  int wg = (blockIdx.x*blockDim.x + t) >> 5;
  int nw = (gridDim.x*blockDim.x) >> 5;
  for (int n = wg; n < NN; n += nw){
    float v0 = hin[(n<<6)+lane], v1 = hin[(n<<6)+32+lane];
    ull ap = sbp[lane];
    #pragma unroll 8
    for (int k = 0; k < 32; k++) ap = ffma2(dup2(__shfl_sync(~0u, v0, k)), sW[k*32+lane], ap);
    #pragma unroll 8
    for (int k = 0; k < 32; k++) ap = ffma2(dup2(__shfl_sync(~0u, v1, k)), sW[(32+k)*32+lane], ap);
    float lo, hi;
    unpk2(ap, lo, hi);
    hmout[n*32+lane] = __floats2half2_rn(fmaxf(lo, 0.f), fmaxf(hi, 0.f));
  }
}

__global__ void k_agg(const __half2* __restrict__ hmin){
  int w = (blockIdx.x*blockDim.x + threadIdx.x) >> 5;
  int lane = threadIdx.x & 31;
  if (w >= NN) return;
  int beg = g_rowptr[w], end = g_rowptr[w+1];
  float ax = 0.f, ay = 0.f;
  int i = beg;
  for (; i + 3 < end; i += 4){
    int2 e0 = g_csr[i], e1 = g_csr[i+1], e2 = g_csr[i+2], e3 = g_csr[i+3];
    float2 f0 = __half22float2(hmin[(size_t)e0.x*32+lane]);
    float2 f1 = __half22float2(hmin[(size_t)e1.x*32+lane]);
    float2 f2 = __half22float2(hmin[(size_t)e2.x*32+lane]);
    float2 f3 = __half22float2(hmin[(size_t)e3.x*32+lane]);
    float a0 = __int_as_float(e0.y), a1 = __int_as_float(e1.y);
    float a2 = __int_as_float(e2.y), a3 = __int_as_float(e3.y);
    ax = fmaf(a0, f0.x, ax); ay = fmaf(a0, f0.y, ay);
    ax = fmaf(a1, f1.x, ax); ay = fmaf(a1, f1.y, ay);
    ax = fmaf(a2, f2.x, ax); ay = fmaf(a2, f2.y, ay);
    ax = fmaf(a3, f3.x, ax); ay = fmaf(a3, f3.y, ay);
  }
  for (; i < end; i++){
    int2 e0 = g_csr[i];
    float a0 = __int_as_float(e0.y);
    float2 f0 = __half22float2(hmin[(size_t)e0.x*32+lane]);
    ax = fmaf(a0, f0.x, ax);
    ay = fmaf(a0, f0.y, ay);
  }
  float inv = 1.f / fmaxf((float)(end - beg), 1.f);
  ((float2*)g_agg)[w*32+lane] = make_float2(ax*inv, ay*inv);
}

#define GRUF_SMEM (14336*8)
__global__ void __launch_bounds__(256,2) k_gruf(const float* __restrict__ hin,
    float* __restrict__ hout, __half2* __restrict__ hmout,
    const float* __restrict__ bih, const float* __restrict__ bhh,
    const float* __restrict__ msb){
  extern __shared__ ull sw[];
  ull* sWi = sw;
  ull* sWh = sw + 6144;
  ull* sHm = sw + 12288;
  __shared__ float sbi[192], sbh[192];
  __shared__ ull sMb[32];
  int t = threadIdx.x;
  for (int i = t; i < 6144; i += 256){ sWi[i] = g_Wih_p[i]; sWh[i] = g_Whh_p[i]; }
  for (int i = t; i < 2048; i += 256) sHm[i] = g_Whm_p[i];
  for (int i = t; i < 192; i += 256){ sbi[i] = bih[i]; sbh[i] = bhh[i]; }
  if (t < 32) sMb[t] = pk2(msb[2*t], msb[2*t+1]);
  __syncthreads();
  int w = t >> 5, lane = t & 31;
  int nchunk = (NN + 31) / 32;
  for (int c = blockIdx.x; c < nchunk; c += gridDim.x){
    int nbase = c*32 + w*4;
    float ra0[4], ra1[4], rh0[4], rh1[4];
    #pragma unroll
    for (int i = 0; i < 4; i++){
      int n = min(nbase + i, NN - 1);
      ra0[i] = g_agg[(n<<6)+lane];
      ra1[i] = g_agg[(n<<6)+32+lane];
      rh0[i] = hin[(n<<6)+lane];
      rh1[i] = hin[(n<<6)+32+lane];
    }
    ull R[4], Z[4], Ng[4], Rh[4], Zh[4], Nh[4];
    gru_core(sWi, sWh, lane, ra0, ra1, rh0, rh1, R, Z, Ng, Rh, Zh, Nh);
    #pragma unroll
    for (int i = 0; i < 4; i++){
      int n = nbase + i;
      bool ok = (n < NN);
      float aL, aH, bL, bH;
      unpk2(R[i], aL, aH);
      unpk2(Rh[i], bL, bH);
      float rL = sigf(aL + sbi[lane] + bL + sbh[lane]);
      float rH = sigf(aH + sbi[lane+32] + bH + sbh[lane+32]);
      unpk2(Z[i], aL, aH);
      unpk2(Zh[i], bL, bH);
      float zL = sigf(aL + sbi[64+lane] + bL + sbh[64+lane]);
      float zH = sigf(aH + sbi[96+lane] + bH + sbh[96+lane]);
      unpk2(Ng[i], aL, aH);
      unpk2(Nh[i], bL, bH);
      float ngL = tanhf(aL + sbi[128+lane] + rL*(bL + sbh[128+lane]));
      float ngH = tanhf(aH + sbi[160+lane] + rH*(bH + sbh[160+lane]));
      float hnL = (1.f - zL)*ngL + zL*rh0[i];
      float hnH = (1.f - zH)*ngH + zH*rh1[i];
      if (ok){
        hout[(n<<6)+lane] = hnL;
        hout[(n<<6)+32+lane] = hnH;
      }
      ull ap = sMb[lane];
      #pragma unroll 8
      for (int k = 0; k < 32; k++) ap = ffma2(dup2(__shfl_sync(~0u, hnL, k)), sHm[k*32+lane], ap);
      #pragma unroll 8
      for (int k = 0; k < 32; k++) ap = ffma2(dup2(__shfl_sync(~0u, hnH, k)), sHm[(32+k)*32+lane], ap);
      float lo, hi;
      unpk2(ap, lo, hi);
      if (ok) hmout[n*32+lane] = __floats2half2_rn(fmaxf(lo, 0.f), fmaxf(hi, 0.f));
    }
  }
}

#define GRU_SMEM (12288*8)
__global__ void __launch_bounds__(256,2) k_gru(const float* __restrict__ hin,
    float* __restrict__ hout, const float* __restrict__ bih,
    const float* __restrict__ bhh){
  extern __shared__ ull sw[];
  ull* sWi = sw;
  ull* sWh = sw + 6144;
  __shared__ float sbi[192], sbh[192];
  int t = threadIdx.x;
  for (int i = t; i < 6144; i += 256){ sWi[i] = g_Wih_p[i]; sWh[i] = g_Whh_p[i]; }
  for (int i = t; i < 192; i += 256){ sbi[i] = bih[i]; sbh[i] = bhh[i]; }
  __syncthreads();
  int w = t >> 5, lane = t & 31;
  int nchunk = (NN + 31) / 32;
  for (int c = blockIdx.x; c < nchunk; c += gridDim.x){
    int nbase = c*32 + w*4;
    float ra0[4], ra1[4], rh0[4], rh1[4];
    #pragma unroll
    for (int i = 0; i < 4; i++){
      int n = min(nbase + i, NN - 1);
      ra0[i] = g_agg[(n<<6)+lane];
      ra1[i] = g_agg[(n<<6)+32+lane];
      rh0[i] = hin[(n<<6)+lane];
      rh1[i] = hin[(n<<6)+32+lane];
    }
    ull R[4], Z[4], Ng[4], Rh[4], Zh[4], Nh[4];
    gru_core(sWi, sWh, lane, ra0, ra1, rh0, rh1, R, Z, Ng, Rh, Zh, Nh);
    #pragma unroll
    for (int i = 0; i < 4; i++){
      int n = nbase + i;
      if (n >= NN) break;
      float aL, aH, bL, bH;
      unpk2(R[i], aL, aH);
      unpk2(Rh[i], bL, bH);
      float rL = sigf(aL + sbi[lane] + bL + sbh[lane]);
      float rH = sigf(aH + sbi[lane+32] + bH + sbh[lane+32]);
      unpk2(Z[i], aL, aH);
      unpk2(Zh[i], bL, bH);
      float zL = sigf(aL + sbi[64+lane] + bL + sbh[64+lane]);
      float zH = sigf(aH + sbi[96+lane] + bH + sbh[96+lane]);
      unpk2(Ng[i], aL, aH);
      unpk2(Nh[i], bL, bH);
      float ngL = tanhf(aL + sbi[128+lane] + rL*(bL + sbh[128+lane]));
      float ngH = tanhf(aH + sbi[160+lane] + rH*(bH + sbh[160+lane]));
      hout[(n<<6)+lane] = (1.f - zL)*ngL + zL*rh0[i];
      hout[(n<<6)+32+lane] = (1.f - zH)*ngH + zH*rh1[i];
    }
  }
}

__global__ void k_AB(const float* __restrict__ hin, const float* __restrict__ b1){
  __shared__ ull sWa[2048], sWb[2048];
  __shared__ ull sbp[32];
  int t = threadIdx.x;
  for (int i = t; i < 2048; i += blockDim.x){ sWa[i] = g_Wa_p[i]; sWb[i] = g_Wb_p[i]; }
  if (t < 32) sbp[t] = pk2(b1[2*t], b1[2*t+1]);
  __syncthreads();
  int lane = t & 31;
  int wg = (blockIdx.x*blockDim.x + t) >> 5;
  int nw = (gridDim.x*blockDim.x) >> 5;
  for (int n = wg; n < NN; n += nw){
    float v0 = hin[(n<<6)+lane], v1 = hin[(n<<6)+32+lane];
    ull aA = sbp[lane], aB = 0ull;
    #pragma unroll 8
    for (int k = 0; k < 32; k++){
      ull v = dup2(__shfl_sync(~0u, v0, k));
      aA = ffma2(v, sWa[k*32+lane], aA);
      aB = ffma2(v, sWb[k*32+lane], aB);
    }
    #pragma unroll 8
    for (int k = 0; k < 32; k++){
      ull v = dup2(__shfl_sync(~0u, v1, k));
      aA = ffma2(v, sWa[(32+k)*32+lane], aA);
      aB = ffma2(v, sWb[(32+k)*32+lane], aB);
    }
    float alo, ahi, blo, bhi;
    unpk2(aA, alo, ahi);
    unpk2(aB, blo, bhi);
    g_Adh[n*32+lane] = __floats2half2_rn(alo, ahi);
    g_Bdh[n*32+lane] = __floats2half2_rn(blo, bhi);
  }
}

__global__ void __launch_bounds__(256) k_dec(const float* __restrict__ ea,
    float* __restrict__ out, const float* __restrict__ b2,
    const float* __restrict__ W3, const float* __restrict__ b3){
  __shared__ __align__(16) ull sW1[160];
  __shared__ __align__(16) ull sW2[1024];
  __shared__ float sW3[128];
  __shared__ float sb2[32], sb3[4];
  __shared__ float sEA[1280];
  int t = threadIdx.x;
  int base = blockIdx.x*256;
  for (int i = t; i < 160; i += 256) sW1[i] = g_W1e_p[i];
  for (int i = t; i < 1024; i += 256) sW2[i] = g_W2_p[i];
  for (int i = t; i < 128; i += 256) sW3[i] = W3[i];
  if (t < 32) sb2[t] = b2[t];
  if (t < 4) sb3[t] = b3[t];
  int lim = MM*5 - base*5;
  for (int i = t; i < 1280 && i < lim; i += 256) sEA[i] = ea[base*5+i];
  __syncthreads();
  int e = base + t;
  if (e >= MM) return;
  int2 sd = g_sd[e];
  const uint4* pA = (const uint4*)&g_Adh[(size_t)sd.x*32];
  const uint4* pB = (const uint4*)&g_Bdh[(size_t)sd.y*32];
  ull s1p[32];
  #pragma unroll
  for (int q = 0; q < 8; q++){
    uint4 av = __ldg(&pA[q]);
    uint4 bv = __ldg(&pB[q]);
    float2 fa, fb;
    fa = __half22float2(*(__half2*)&av.x);
    fb = __half22float2(*(__half2*)&bv.x);
    s1p[4*q+0] = pk2(fa.x+fb.x, fa.y+fb.y);
    fa = __half22float2(*(__half2*)&av.y);
    fb = __half22float2(*(__half2*)&bv.y);
    s1p[4*q+1] = pk2(fa.x+fb.x, fa.y+fb.y);
    fa = __half22float2(*(__half2*)&av.z);
    fb = __half22float2(*(__half2*)&bv.z);
    s1p[4*q+2] = pk2(fa.x+fb.x, fa.y+fb.y);
    fa = __half22float2(*(__half2*)&av.w);
    fb = __half22float2(*(__half2*)&bv.w);
    s1p[4*q+3] = pk2(fa.x+fb.x, fa.y+fb.y);
  }
  const ulonglong2* w1 = (const ulonglong2*)sW1;
  #pragma unroll
  for (int k = 0; k < 5; k++){
    ull ev = dup2(sEA[t*5+k]);
    #pragma unroll
    for (int q = 0; q < 16; q++){
      ulonglong2 wq = w1[k*16+q];
      s1p[2*q] = ffma2(ev, wq.x, s1p[2*q]);
      s1p[2*q+1] = ffma2(ev, wq.y, s1p[2*q+1]);
    }
  }
  float s1[64];
  #pragma unroll
  for (int p = 0; p < 32; p++){
    float lo, hi;
    unpk2(s1p[p], lo, hi);
    s1[2*p] = fmaxf(lo, 0.f);
    s1[2*p+1] = fmaxf(hi, 0.f);
  }
  ull a2p[16];
  #pragma unroll
  for (int jp = 0; jp < 16; jp++) a2p[jp] = pk2(sb2[2*jp], sb2[2*jp+1]);
  const ulonglong2* w2 = (const ulonglong2*)sW2;
  #pragma unroll 8
  for (int k = 0; k < 64; k++){
    ull sdv = dup2(s1[k]);
    #pragma unroll
    for (int q = 0; q < 8; q++){
      ulonglong2 wq = w2[k*8+q];
      a2p[2*q] = ffma2(sdv, wq.x, a2p[2*q]);
      a2p[2*q+1] = ffma2(sdv, wq.y, a2p[2*q+1]);
    }
  }
  float a2[32];
  #pragma unroll
  for (int jp = 0; jp < 16; jp++){
    float lo, hi;
    unpk2(a2p[jp], lo, hi);
    a2[2*jp] = fmaxf(lo, 0.f);
    a2[2*jp+1] = fmaxf(hi, 0.f);
  }
  float o0 = sb3[0], o1 = sb3[1], o2 = sb3[2], o3 = sb3[3];
  #pragma unroll
  for (int q = 0; q < 32; q++){
    float v = a2[q];
    o0 = fmaf(v, sW3[q], o0);
    o1 = fmaf(v, sW3[32+q], o1);
    o2 = fmaf(v, sW3[64+q], o2);
    o3 = fmaf(v, sW3[96+q], o3);
  }
  ((float4*)out)[e] = make_float4(o0, o1, o2, o3);
}

extern "C" void kernel_launch(void* const* d_in, const int* in_sizes, int n_in,
                              void* d_out, int out_size){
  (void)in_sizes; (void)n_in; (void)out_size;
  const float* x   = (const float*)d_in[0];
  const void*  ei  = d_in[1];
  const float* ea  = (const float*)d_in[2];
  const float* u   = (const float*)d_in[3];
  const float* Win = (const float*)d_in[4];
  const float* bin = (const float*)d_in[5];
  const float* eW1 = (const float*)d_in[6];
  const float* eb1 = (const float*)d_in[7];
  const float* eW2 = (const float*)d_in[8];
  const float* eb2 = (const float*)d_in[9];
  const float* msW = (const float*)d_in[10];
  const float* msb = (const float*)d_in[11];
  const float* Wih = (const float*)d_in[12];
  const float* bih = (const float*)d_in[13];
  const float* Whh = (const float*)d_in[14];
  const float* bhh = (const float*)d_in[15];
  const float* dW1 = (const float*)d_in[16];
  const float* db1 = (const float*)d_in[17];
  const float* dW2 = (const float*)d_in[18];
  const float* db2 = (const float*)d_in[19];
  const float* dW3 = (const float*)d_in[20];
  const float* db3 = (const float*)d_in[21];
  float* out = (float*)d_out;

  static int init_done = 0;
  static cudaStream_t s1;
  static cudaEvent_t evA, evB;
  if (!init_done){
    cudaFuncSetAttribute(k_gru,  cudaFuncAttributeMaxDynamicSharedMemorySize, GRU_SMEM);
    cudaFuncSetAttribute(k_gruf, cudaFuncAttributeMaxDynamicSharedMemorySize, GRUF_SMEM);
    cudaStreamCreateWithFlags(&s1, cudaStreamNonBlocking);
    cudaEventCreateWithFlags(&evA, cudaEventDisableTiming);
    cudaEventCreateWithFlags(&evB, cudaEventDisableTiming);
    init_done = 1;
  }

  float *hA_p = 0, *hB_p = 0;
  __half2 *hmA_p = 0, *hmB_p = 0;
  cudaGetSymbolAddress((void**)&hA_p, g_hA);
  cudaGetSymbolAddress((void**)&hB_p, g_hB);
  cudaGetSymbolAddress((void**)&hmA_p, g_hmA);
  cudaGetSymbolAddress((void**)&hmB_p, g_hmB);

  k_init<<<251, 256>>>((const int*)ei, Wih, Whh, dW2, dW1, msW, eW1, eb1, eW2, Win, bin, u);

  cudaEventRecord(evA, 0);
  cudaStreamWaitEvent(s1, evA, 0);

  k_h2<<<(NN*64 + 255)/256, 256, 0, s1>>>(x, Win);
  k_hm0<<<1184, 256, 0, s1>>>(hA_p, hmA_p, msb);
  cudaEventRecord(evB, s1);

  k_count<<<(MM/2 + 255)/256, 256>>>(ei);
  k_scan1<<<196, 256>>>();
  k_scan2<<<1, 256>>>();
  k_scan3<<<196, 256>>>();
  k_prep2<<<(MM + 255)/256, 256>>>(ei, ea, eb2);

  cudaStreamWaitEvent(0, evB, 0);

  const int GRID_AGG = (NN*32 + 255)/256;
  k_agg<<<GRID_AGG, 256>>>(hmA_p);
  k_gruf<<<296, 256, GRUF_SMEM>>>(hA_p, hB_p, hmB_p, bih, bhh, msb);

  k_agg<<<GRID_AGG, 256>>>(hmB_p);
  k_gruf<<<296, 256, GRUF_SMEM>>>(hB_p, hA_p, hmA_p, bih, bhh, msb);

  k_agg<<<GRID_AGG, 256>>>(hmA_p);
  k_gru<<<296, 256, GRU_SMEM>>>(hA_p, hB_p, bih, bhh);

  k_AB<<<1184, 256>>>(hB_p, db1);
  k_dec<<<(MM + 255)/256, 256>>>(ea, out, db2, dW3, db3);
}